// round 2
// baseline (speedup 1.0000x reference)
#include <cuda_runtime.h>
#include <cuda_bf16.h>
#include <math.h>

// ---------------------------------------------------------------------------
// Problem constants
// ---------------------------------------------------------------------------
#define B_   2
#define T_   1024
#define D_   1024
#define H_   16
#define HD_  64
#define L_   8
#define DFF_ 4096
#define V_   32000
#define BT_  (B_ * T_)          // 2048
#define BH_  (B_ * H_)          // 32
#define EPS_ 1e-5f

// ---------------------------------------------------------------------------
// Scratch (device globals; allocation-free per harness rules). 80 MB total.
// ---------------------------------------------------------------------------
__device__ float g_x[BT_ * D_];            //  8 MB residual stream
__device__ float g_xn[BT_ * D_];           //  8 MB layernorm output
__device__ float g_qkv[BT_ * 3 * D_];      // 24 MB
__device__ float g_attn[BT_ * D_];         //  8 MB attention output (pre-proj)
__device__ float g_h[BT_ * DFF_];          // 32 MB FFN hidden

// ---------------------------------------------------------------------------
// Embedding + sinusoidal positional encoding
// ---------------------------------------------------------------------------
__global__ __launch_bounds__(256) void embed_kernel(
    const int* __restrict__ idx, const float* __restrict__ embed,
    float* __restrict__ x)
{
    int bt  = blockIdx.x;
    int t   = bt % T_;
    int tok = idx[bt];
    const float neg_log_1e4_over_d = -logf(10000.0f) / (float)D_;
    int d0 = threadIdx.x * 4;
    const float* erow = embed + (size_t)tok * D_;
    float* xrow = x + (size_t)bt * D_;
    float4 e = *reinterpret_cast<const float4*>(erow + d0);
    float out[4] = {e.x, e.y, e.z, e.w};
#pragma unroll
    for (int i = 0; i < 4; i++) {
        int d = d0 + i;
        int i2 = d & ~1;  // even base
        float ang = (float)t * expf((float)i2 * neg_log_1e4_over_d);
        float pe = (d & 1) ? cosf(ang) : sinf(ang);
        out[i] += pe;
    }
    *reinterpret_cast<float4*>(xrow + d0) =
        make_float4(out[0], out[1], out[2], out[3]);
}

// ---------------------------------------------------------------------------
// LayerNorm: one block per row (1024 elems), 256 threads * 4 elems
// ---------------------------------------------------------------------------
__global__ __launch_bounds__(256) void layernorm_kernel(
    const float* __restrict__ x, const float* __restrict__ g,
    const float* __restrict__ b, float* __restrict__ y)
{
    __shared__ float red[256];
    int row = blockIdx.x;
    int tid = threadIdx.x;
    const float* xr = x + (size_t)row * D_;
    float4 v = reinterpret_cast<const float4*>(xr)[tid];

    float s = v.x + v.y + v.z + v.w;
    red[tid] = s;
    __syncthreads();
    for (int off = 128; off > 0; off >>= 1) {
        if (tid < off) red[tid] += red[tid + off];
        __syncthreads();
    }
    float mu = red[0] * (1.0f / D_);
    __syncthreads();

    float d0 = v.x - mu, d1 = v.y - mu, d2 = v.z - mu, d3 = v.w - mu;
    red[tid] = d0 * d0 + d1 * d1 + d2 * d2 + d3 * d3;
    __syncthreads();
    for (int off = 128; off > 0; off >>= 1) {
        if (tid < off) red[tid] += red[tid + off];
        __syncthreads();
    }
    float var = red[0] * (1.0f / D_);
    float rs = rsqrtf(var + EPS_);

    int d = tid * 4; (void)d;
    float4 gg = reinterpret_cast<const float4*>(g)[tid];
    float4 bb = reinterpret_cast<const float4*>(b)[tid];
    float4 o;
    o.x = d0 * rs * gg.x + bb.x;
    o.y = d1 * rs * gg.y + bb.y;
    o.z = d2 * rs * gg.z + bb.z;
    o.w = d3 * rs * gg.w + bb.w;
    reinterpret_cast<float4*>(y + (size_t)row * D_)[tid] = o;
}

// ---------------------------------------------------------------------------
// SGEMM: C[M,N] = A[M,K] @ B[K,N] (+bias[N]) (+res[M,N]) (relu?)
// BM=128, BN=128, BK=16; 256 threads; 8x8 outputs per thread.
// All shapes used divide tiles exactly (M=2048; N in {1024,3072,4096,32000};
// K in {1024,4096}) -> no bounds checks.
// ---------------------------------------------------------------------------
#define BM 128
#define BN 128
#define BK 16
#define APAD 132   // As row stride (4-word multiple for aligned float4 reads)
#define BPAD 132

__global__ __launch_bounds__(256) void sgemm_kernel(
    const float* __restrict__ A, const float* __restrict__ B,
    const float* __restrict__ bias, const float* __restrict__ res,
    float* __restrict__ C, int M, int N, int K, int relu)
{
    __shared__ float As[BK * APAD];   // As[k][m], stride APAD
    __shared__ float Bs[BK * BPAD];   // Bs[k][n], stride BPAD

    int bx = blockIdx.x;   // N tile
    int by = blockIdx.y;   // M tile
    int tid = threadIdx.x;
    int tx = tid & 15;     // 0..15 (col group)
    int ty = tid >> 4;     // 0..15 (row group)
    int row0 = by * BM + ty * 8;
    int col0 = bx * BN + tx * 8;

    float acc[8][8];
#pragma unroll
    for (int i = 0; i < 8; i++)
#pragma unroll
        for (int j = 0; j < 8; j++) acc[i][j] = 0.0f;

    for (int k0 = 0; k0 < K; k0 += BK) {
        // A tile 128x16 -> 512 float4 (2/thread); store transposed As[k][m]
#pragma unroll
        for (int i = 0; i < 2; i++) {
            int id = tid + i * 256;
            int ar = id >> 2;           // 0..127
            int ac = (id & 3) * 4;      // 0,4,8,12
            float4 v = *reinterpret_cast<const float4*>(
                &A[(size_t)(by * BM + ar) * K + k0 + ac]);
            As[(ac + 0) * APAD + ar] = v.x;
            As[(ac + 1) * APAD + ar] = v.y;
            As[(ac + 2) * APAD + ar] = v.z;
            As[(ac + 3) * APAD + ar] = v.w;
        }
        // B tile 16x128 -> 512 float4 (2/thread)
#pragma unroll
        for (int i = 0; i < 2; i++) {
            int id = tid + i * 256;
            int br = id >> 5;           // 0..15
            int bc = (id & 31) * 4;     // 0..124
            *reinterpret_cast<float4*>(&Bs[br * BPAD + bc]) =
                *reinterpret_cast<const float4*>(
                    &B[(size_t)(k0 + br) * N + bx * BN + bc]);
        }
        __syncthreads();
#pragma unroll
        for (int k = 0; k < BK; k++) {
            float a[8], bb[8];
            *reinterpret_cast<float4*>(&a[0]) =
                *reinterpret_cast<const float4*>(&As[k * APAD + ty * 8]);
            *reinterpret_cast<float4*>(&a[4]) =
                *reinterpret_cast<const float4*>(&As[k * APAD + ty * 8 + 4]);
            *reinterpret_cast<float4*>(&bb[0]) =
                *reinterpret_cast<const float4*>(&Bs[k * BPAD + tx * 8]);
            *reinterpret_cast<float4*>(&bb[4]) =
                *reinterpret_cast<const float4*>(&Bs[k * BPAD + tx * 8 + 4]);
#pragma unroll
            for (int i = 0; i < 8; i++)
#pragma unroll
                for (int j = 0; j < 8; j++)
                    acc[i][j] = fmaf(a[i], bb[j], acc[i][j]);
        }
        __syncthreads();
    }

#pragma unroll
    for (int i = 0; i < 8; i++) {
#pragma unroll
        for (int jj = 0; jj < 2; jj++) {
            size_t off = (size_t)(row0 + i) * N + col0 + jj * 4;
            float4 r = res ? *reinterpret_cast<const float4*>(&res[off])
                           : make_float4(0.f, 0.f, 0.f, 0.f);
            float4 bs = bias ? *reinterpret_cast<const float4*>(&bias[col0 + jj * 4])
                             : make_float4(0.f, 0.f, 0.f, 0.f);
            float4 o;
            o.x = acc[i][jj * 4 + 0] + bs.x + r.x;
            o.y = acc[i][jj * 4 + 1] + bs.y + r.y;
            o.z = acc[i][jj * 4 + 2] + bs.z + r.z;
            o.w = acc[i][jj * 4 + 3] + bs.w + r.w;
            if (relu) {
                o.x = fmaxf(o.x, 0.f); o.y = fmaxf(o.y, 0.f);
                o.z = fmaxf(o.z, 0.f); o.w = fmaxf(o.w, 0.f);
            }
            *reinterpret_cast<float4*>(&C[off]) = o;
        }
    }
}

// ---------------------------------------------------------------------------
// Fused causal flash attention (fp32, online softmax).
// grid (T/64 q-tiles, BH), 256 threads. Q tile 64x64 held in smem; iterate
// causal K/V tiles of 64. Each thread owns a 4x4 microtile of S and of O.
// Row group ty (16 lanes of one warp) owns output rows ty*4..+3.
// smem (floats): Qs[64*65] | U = Ks[64*65] / Ps[64*68] (aliased) | Vs[64*64]
// ---------------------------------------------------------------------------
#define QS_STRIDE 65
#define KS_STRIDE 65
#define PS_STRIDE 68
#define VS_STRIDE 64
#define FA_SMEM_FLOATS (64 * QS_STRIDE + 64 * PS_STRIDE + 64 * VS_STRIDE)

__global__ __launch_bounds__(256) void flash_attn_kernel(
    const float* __restrict__ qkv, float* __restrict__ out)
{
    extern __shared__ float sm[];
    float* Qs = sm;                       // [q][d] stride 65
    float* U  = sm + 64 * QS_STRIDE;      // Ks [k][d] s65  /  Ps [k][q] s68
    float* Vs = U + 64 * PS_STRIDE;       // [k][c] stride 64

    int qt = blockIdx.x, bh = blockIdx.y;
    int b = bh >> 4, h = bh & 15;
    int tid = threadIdx.x;
    int tx = tid & 15;   // S col group / O col group
    int ty = tid >> 4;   // S row group / O row group

    // ---- load Q tile (rows qt*64..): 1024 float4, 4 per thread ----
#pragma unroll
    for (int it = 0; it < 4; it++) {
        int idx = tid + it * 256;
        int r = idx >> 4;            // 0..63
        int c = (idx & 15) * 4;      // 0..60
        float4 v = *reinterpret_cast<const float4*>(
            &qkv[(size_t)(b * T_ + qt * 64 + r) * (3 * D_) + h * HD_ + c]);
        Qs[r * QS_STRIDE + c + 0] = v.x;
        Qs[r * QS_STRIDE + c + 1] = v.y;
        Qs[r * QS_STRIDE + c + 2] = v.z;
        Qs[r * QS_STRIDE + c + 3] = v.w;
    }

    float m[4], l[4], acc[4][4];
#pragma unroll
    for (int i = 0; i < 4; i++) {
        m[i] = -INFINITY; l[i] = 0.0f;
#pragma unroll
        for (int j = 0; j < 4; j++) acc[i][j] = 0.0f;
    }

    for (int kt = 0; kt <= qt; kt++) {
        __syncthreads();   // prev-iter Ps/Vs reads done before overwrite
        // ---- load K and V tiles ----
#pragma unroll
        for (int it = 0; it < 4; it++) {
            int idx = tid + it * 256;
            int r = idx >> 4;
            int c = (idx & 15) * 4;
            size_t base = (size_t)(b * T_ + kt * 64 + r) * (3 * D_) + h * HD_ + c;
            float4 kv = *reinterpret_cast<const float4*>(&qkv[base + D_]);
            U[r * KS_STRIDE + c + 0] = kv.x;
            U[r * KS_STRIDE + c + 1] = kv.y;
            U[r * KS_STRIDE + c + 2] = kv.z;
            U[r * KS_STRIDE + c + 3] = kv.w;
            float4 vv = *reinterpret_cast<const float4*>(&qkv[base + 2 * D_]);
            *reinterpret_cast<float4*>(&Vs[r * VS_STRIDE + c]) = vv;
        }
        __syncthreads();

        // ---- S = Q K^T / 8 ----
        float s[4][4];
#pragma unroll
        for (int i = 0; i < 4; i++)
#pragma unroll
            for (int j = 0; j < 4; j++) s[i][j] = 0.0f;
#pragma unroll 8
        for (int d = 0; d < HD_; d++) {
            float a[4], kk[4];
#pragma unroll
            for (int i = 0; i < 4; i++) a[i] = Qs[(ty * 4 + i) * QS_STRIDE + d];
#pragma unroll
            for (int j = 0; j < 4; j++) kk[j] = U[(tx * 4 + j) * KS_STRIDE + d];
#pragma unroll
            for (int i = 0; i < 4; i++)
#pragma unroll
                for (int j = 0; j < 4; j++)
                    s[i][j] = fmaf(a[i], kk[j], s[i][j]);
        }

        // ---- scale + causal mask ----
        bool diag = (kt == qt);
#pragma unroll
        for (int i = 0; i < 4; i++)
#pragma unroll
            for (int j = 0; j < 4; j++) {
                s[i][j] *= 0.125f;
                if (diag && (tx * 4 + j > ty * 4 + i)) s[i][j] = -INFINITY;
            }

        // ---- online softmax update (row reduce across 16 lanes) ----
        float p[4][4];
#pragma unroll
        for (int i = 0; i < 4; i++) {
            float mt = fmaxf(fmaxf(s[i][0], s[i][1]), fmaxf(s[i][2], s[i][3]));
#pragma unroll
            for (int off = 8; off > 0; off >>= 1)
                mt = fmaxf(mt, __shfl_xor_sync(0xffffffffu, mt, off));
            float m_new = fmaxf(m[i], mt);
            float sc = expf(m[i] - m_new);     // 0 if m was -inf
            float rs = 0.0f;
#pragma unroll
            for (int j = 0; j < 4; j++) {
                p[i][j] = expf(s[i][j] - m_new);
                rs += p[i][j];
            }
#pragma unroll
            for (int off = 8; off > 0; off >>= 1)
                rs += __shfl_xor_sync(0xffffffffu, rs, off);
            l[i] = l[i] * sc + rs;
            m[i] = m_new;
#pragma unroll
            for (int j = 0; j < 4; j++) acc[i][j] *= sc;
        }

        __syncthreads();   // Ks reads done; safe to overwrite U with Ps

        // ---- store P transposed: Ps[k][q] ----
#pragma unroll
        for (int j = 0; j < 4; j++) {
            *reinterpret_cast<float4*>(&U[(tx * 4 + j) * PS_STRIDE + ty * 4]) =
                make_float4(p[0][j], p[1][j], p[2][j], p[3][j]);
        }
        __syncthreads();

        // ---- O += P V ----
#pragma unroll 8
        for (int k = 0; k < 64; k++) {
            float4 a4 = *reinterpret_cast<const float4*>(&U[k * PS_STRIDE + ty * 4]);
            float4 v4 = *reinterpret_cast<const float4*>(&Vs[k * VS_STRIDE + tx * 4]);
            float a[4] = {a4.x, a4.y, a4.z, a4.w};
            float v[4] = {v4.x, v4.y, v4.z, v4.w};
#pragma unroll
            for (int i = 0; i < 4; i++)
#pragma unroll
                for (int j = 0; j < 4; j++)
                    acc[i][j] = fmaf(a[i], v[j], acc[i][j]);
        }
    }

    // ---- normalize + write ----
#pragma unroll
    for (int i = 0; i < 4; i++) {
        float inv = 1.0f / l[i];
        size_t off = (size_t)(b * T_ + qt * 64 + ty * 4 + i) * D_ + h * HD_ + tx * 4;
        *reinterpret_cast<float4*>(&out[off]) = make_float4(
            acc[i][0] * inv, acc[i][1] * inv, acc[i][2] * inv, acc[i][3] * inv);
    }
}

// ---------------------------------------------------------------------------
// Host launch
// ---------------------------------------------------------------------------
extern "C" void kernel_launch(void* const* d_in, const int* in_sizes, int n_in,
                              void* d_out, int out_size)
{
    const int*   idx   = (const int*)  d_in[0];
    const float* embed = (const float*)d_in[1];
    const float* Wqkv  = (const float*)d_in[2];   // [L, D, 3D]
    const float* Wproj = (const float*)d_in[3];   // [L, D, D]
    const float* bproj = (const float*)d_in[4];   // [L, D]
    const float* ln1_g = (const float*)d_in[5];
    const float* ln1_b = (const float*)d_in[6];
    const float* ln2_g = (const float*)d_in[7];
    const float* ln2_b = (const float*)d_in[8];
    const float* W1    = (const float*)d_in[9];   // [L, D, DFF]
    const float* b1    = (const float*)d_in[10];  // [L, DFF]
    const float* W2    = (const float*)d_in[11];  // [L, DFF, D]
    const float* b2    = (const float*)d_in[12];  // [L, D]
    const float* lnf_g = (const float*)d_in[13];
    const float* lnf_b = (const float*)d_in[14];
    const float* Whead = (const float*)d_in[15];  // [D, V]
    float* out = (float*)d_out;

    float *x, *xn, *qkv, *attn, *hbuf;
    cudaGetSymbolAddress((void**)&x,    g_x);
    cudaGetSymbolAddress((void**)&xn,   g_xn);
    cudaGetSymbolAddress((void**)&qkv,  g_qkv);
    cudaGetSymbolAddress((void**)&attn, g_attn);
    cudaGetSymbolAddress((void**)&hbuf, g_h);

    static int fa_smem_set = 0;
    int fa_smem_bytes = FA_SMEM_FLOATS * (int)sizeof(float);  // 50432
    if (!fa_smem_set) {
        cudaFuncSetAttribute(flash_attn_kernel,
                             cudaFuncAttributeMaxDynamicSharedMemorySize,
                             fa_smem_bytes);
        fa_smem_set = 1;
    }

    embed_kernel<<<BT_, 256>>>(idx, embed, x);

    for (int l = 0; l < L_; l++) {
        const float* wqkv_l  = Wqkv  + (size_t)l * D_ * 3 * D_;
        const float* wproj_l = Wproj + (size_t)l * D_ * D_;
        const float* bproj_l = bproj + (size_t)l * D_;
        const float* w1_l    = W1    + (size_t)l * D_ * DFF_;
        const float* b1_l    = b1    + (size_t)l * DFF_;
        const float* w2_l    = W2    + (size_t)l * DFF_ * D_;
        const float* b2_l    = b2    + (size_t)l * D_;

        layernorm_kernel<<<BT_, 256>>>(x, ln1_g + (size_t)l * D_,
                                       ln1_b + (size_t)l * D_, xn);
        sgemm_kernel<<<dim3(3 * D_ / BN, BT_ / BM), 256>>>(
            xn, wqkv_l, nullptr, nullptr, qkv, BT_, 3 * D_, D_, 0);
        flash_attn_kernel<<<dim3(T_ / 64, BH_), 256, fa_smem_bytes>>>(qkv, attn);
        sgemm_kernel<<<dim3(D_ / BN, BT_ / BM), 256>>>(
            attn, wproj_l, bproj_l, x, x, BT_, D_, D_, 0);
        layernorm_kernel<<<BT_, 256>>>(x, ln2_g + (size_t)l * D_,
                                       ln2_b + (size_t)l * D_, xn);
        sgemm_kernel<<<dim3(DFF_ / BN, BT_ / BM), 256>>>(
            xn, w1_l, b1_l, nullptr, hbuf, BT_, DFF_, D_, 1);
        sgemm_kernel<<<dim3(D_ / BN, BT_ / BM), 256>>>(
            hbuf, w2_l, b2_l, x, x, BT_, D_, DFF_, 0);
    }

    layernorm_kernel<<<BT_, 256>>>(x, lnf_g, lnf_b, xn);
    sgemm_kernel<<<dim3(V_ / BN, BT_ / BM), 256>>>(
        xn, Whead, nullptr, nullptr, out, BT_, V_, D_, 0);
}

// round 3
// speedup vs baseline: 2.0202x; 2.0202x over previous
#include <cuda_runtime.h>
#include <cuda_bf16.h>
#include <math.h>
#include <stdint.h>

// ---------------------------------------------------------------------------
// Problem constants
// ---------------------------------------------------------------------------
#define B_   2
#define T_   1024
#define D_   1024
#define H_   16
#define HD_  64
#define L_   8
#define DFF_ 4096
#define V_   32000
#define BT_  (B_ * T_)          // 2048
#define BH_  (B_ * H_)          // 32
#define EPS_ 1e-5f

// ---------------------------------------------------------------------------
// Scratch (device globals; allocation-free per harness rules). 80 MB total.
// ---------------------------------------------------------------------------
__device__ float g_x[BT_ * D_];            //  8 MB residual stream
__device__ float g_xn[BT_ * D_];           //  8 MB layernorm output
__device__ float g_qkv[BT_ * 3 * D_];      // 24 MB
__device__ float g_attn[BT_ * D_];         //  8 MB attention output (pre-proj)
__device__ float g_h[BT_ * DFF_];          // 32 MB FFN hidden

// ---------------------------------------------------------------------------
// Helpers: fp32 -> tf32 (round to nearest) and the tf32 MMA
// ---------------------------------------------------------------------------
__device__ __forceinline__ uint32_t f2tf32(float x) {
    uint32_t u;
    asm("cvt.rna.tf32.f32 %0, %1;" : "=r"(u) : "f"(x));
    return u;
}

__device__ __forceinline__ void mma_tf32(
    float& c0, float& c1, float& c2, float& c3,
    uint32_t a0, uint32_t a1, uint32_t a2, uint32_t a3,
    uint32_t b0, uint32_t b1)
{
    asm volatile(
        "mma.sync.aligned.m16n8k8.row.col.f32.tf32.tf32.f32 "
        "{%0,%1,%2,%3}, {%4,%5,%6,%7}, {%8,%9}, {%0,%1,%2,%3};"
        : "+f"(c0), "+f"(c1), "+f"(c2), "+f"(c3)
        : "r"(a0), "r"(a1), "r"(a2), "r"(a3), "r"(b0), "r"(b1));
}

// ---------------------------------------------------------------------------
// Embedding + sinusoidal positional encoding
// ---------------------------------------------------------------------------
__global__ __launch_bounds__(256) void embed_kernel(
    const int* __restrict__ idx, const float* __restrict__ embed,
    float* __restrict__ x)
{
    int bt  = blockIdx.x;
    int t   = bt % T_;
    int tok = idx[bt];
    const float neg_log_1e4_over_d = -logf(10000.0f) / (float)D_;
    int d0 = threadIdx.x * 4;
    const float* erow = embed + (size_t)tok * D_;
    float* xrow = x + (size_t)bt * D_;
    float4 e = *reinterpret_cast<const float4*>(erow + d0);
    float out[4] = {e.x, e.y, e.z, e.w};
#pragma unroll
    for (int i = 0; i < 4; i++) {
        int d = d0 + i;
        int i2 = d & ~1;
        float ang = (float)t * expf((float)i2 * neg_log_1e4_over_d);
        float pe = (d & 1) ? cosf(ang) : sinf(ang);
        out[i] += pe;
    }
    *reinterpret_cast<float4*>(xrow + d0) =
        make_float4(out[0], out[1], out[2], out[3]);
}

// ---------------------------------------------------------------------------
// LayerNorm: one block per row (1024 elems), 256 threads * 4 elems
// ---------------------------------------------------------------------------
__global__ __launch_bounds__(256) void layernorm_kernel(
    const float* __restrict__ x, const float* __restrict__ g,
    const float* __restrict__ b, float* __restrict__ y)
{
    __shared__ float red[256];
    int row = blockIdx.x;
    int tid = threadIdx.x;
    const float* xr = x + (size_t)row * D_;
    float4 v = reinterpret_cast<const float4*>(xr)[tid];

    float s = v.x + v.y + v.z + v.w;
    red[tid] = s;
    __syncthreads();
    for (int off = 128; off > 0; off >>= 1) {
        if (tid < off) red[tid] += red[tid + off];
        __syncthreads();
    }
    float mu = red[0] * (1.0f / D_);
    __syncthreads();

    float d0 = v.x - mu, d1 = v.y - mu, d2 = v.z - mu, d3 = v.w - mu;
    red[tid] = d0 * d0 + d1 * d1 + d2 * d2 + d3 * d3;
    __syncthreads();
    for (int off = 128; off > 0; off >>= 1) {
        if (tid < off) red[tid] += red[tid + off];
        __syncthreads();
    }
    float var = red[0] * (1.0f / D_);
    float rs = rsqrtf(var + EPS_);

    float4 gg = reinterpret_cast<const float4*>(g)[tid];
    float4 bb = reinterpret_cast<const float4*>(b)[tid];
    float4 o;
    o.x = d0 * rs * gg.x + bb.x;
    o.y = d1 * rs * gg.y + bb.y;
    o.z = d2 * rs * gg.z + bb.z;
    o.w = d3 * rs * gg.w + bb.w;
    reinterpret_cast<float4*>(y + (size_t)row * D_)[tid] = o;
}

// ---------------------------------------------------------------------------
// Tensor-core SGEMM (tf32 mma.sync): C = A@B (+bias) (+res) (relu?)
// BM=BN=128, BK=16. 256 threads = 8 warps in 2(M) x 4(N); warp tile 64x32.
// Each warp: 4x4 grid of m16n8k8 mma, 2 k-steps per BK tile.
// smem: As[k][m] / Bs[k][n] as tf32 (uint32), row stride 136 (conflict-free
// fragment reads: 136 mod 32 == 8).
// All shapes divide tiles exactly -> no bounds checks.
// ---------------------------------------------------------------------------
#define BM 128
#define BN 128
#define BK 16
#define SSTR 136

__global__ __launch_bounds__(256) void sgemm_tc_kernel(
    const float* __restrict__ A, const float* __restrict__ B,
    const float* __restrict__ bias, const float* __restrict__ res,
    float* __restrict__ C, int M, int N, int K, int relu)
{
    __shared__ uint32_t As[BK * SSTR];   // As[k*SSTR + m]
    __shared__ uint32_t Bs[BK * SSTR];   // Bs[k*SSTR + n]

    int bx = blockIdx.x;   // N tile
    int by = blockIdx.y;   // M tile
    int tid  = threadIdx.x;
    int wid  = tid >> 5;
    int lane = tid & 31;
    int lq   = lane >> 2;   // 0..7
    int lr   = lane & 3;    // 0..3

    int warp_m = wid & 1;          // 0..1
    int warp_n = wid >> 1;         // 0..3
    int wm0 = warp_m * 64;         // warp M base within tile
    int wn0 = warp_n * 32;         // warp N base within tile

    float acc[4][4][4];
#pragma unroll
    for (int i = 0; i < 4; i++)
#pragma unroll
        for (int j = 0; j < 4; j++)
#pragma unroll
            for (int r = 0; r < 4; r++) acc[i][j][r] = 0.0f;

    for (int k0 = 0; k0 < K; k0 += BK) {
        // ---- A tile 128x16 -> As[k][m] (transpose + tf32) ----
#pragma unroll
        for (int it = 0; it < 2; it++) {
            int id = tid + it * 256;
            int ar = id >> 2;            // m: 0..127
            int ac = (id & 3) * 4;       // k: 0,4,8,12
            float4 v = *reinterpret_cast<const float4*>(
                &A[(size_t)(by * BM + ar) * K + k0 + ac]);
            As[(ac + 0) * SSTR + ar] = f2tf32(v.x);
            As[(ac + 1) * SSTR + ar] = f2tf32(v.y);
            As[(ac + 2) * SSTR + ar] = f2tf32(v.z);
            As[(ac + 3) * SSTR + ar] = f2tf32(v.w);
        }
        // ---- B tile 16x128 -> Bs[k][n] (tf32, vectorized) ----
#pragma unroll
        for (int it = 0; it < 2; it++) {
            int id = tid + it * 256;
            int br = id >> 5;            // k: 0..15
            int bc = (id & 31) * 4;      // n: 0..124
            float4 v = *reinterpret_cast<const float4*>(
                &B[(size_t)(k0 + br) * N + bx * BN + bc]);
            uint4 u;
            u.x = f2tf32(v.x); u.y = f2tf32(v.y);
            u.z = f2tf32(v.z); u.w = f2tf32(v.w);
            *reinterpret_cast<uint4*>(&Bs[br * SSTR + bc]) = u;
        }
        __syncthreads();

#pragma unroll
        for (int ks = 0; ks < BK; ks += 8) {
            // fragments
            uint32_t af[4][4], bf[4][2];
#pragma unroll
            for (int i = 0; i < 4; i++) {
                int m = wm0 + i * 16 + lq;
                af[i][0] = As[(ks + lr)     * SSTR + m];
                af[i][1] = As[(ks + lr)     * SSTR + m + 8];
                af[i][2] = As[(ks + lr + 4) * SSTR + m];
                af[i][3] = As[(ks + lr + 4) * SSTR + m + 8];
            }
#pragma unroll
            for (int j = 0; j < 4; j++) {
                int n = wn0 + j * 8 + lq;
                bf[j][0] = Bs[(ks + lr)     * SSTR + n];
                bf[j][1] = Bs[(ks + lr + 4) * SSTR + n];
            }
#pragma unroll
            for (int i = 0; i < 4; i++)
#pragma unroll
                for (int j = 0; j < 4; j++)
                    mma_tf32(acc[i][j][0], acc[i][j][1],
                             acc[i][j][2], acc[i][j][3],
                             af[i][0], af[i][1], af[i][2], af[i][3],
                             bf[j][0], bf[j][1]);
        }
        __syncthreads();
    }

    // ---- epilogue: C fragment = (row lq / lq+8, col 2*lr / 2*lr+1) ----
    int rowbase = by * BM + wm0;
    int colbase = bx * BN + wn0;
#pragma unroll
    for (int i = 0; i < 4; i++) {
#pragma unroll
        for (int j = 0; j < 4; j++) {
            int col = colbase + j * 8 + lr * 2;
#pragma unroll
            for (int half = 0; half < 2; half++) {
                int row = rowbase + i * 16 + lq + half * 8;
                size_t off = (size_t)row * N + col;
                float v0 = acc[i][j][half * 2 + 0];
                float v1 = acc[i][j][half * 2 + 1];
                if (bias) {
                    float2 bs = *reinterpret_cast<const float2*>(&bias[col]);
                    v0 += bs.x; v1 += bs.y;
                }
                if (res) {
                    float2 rr = *reinterpret_cast<const float2*>(&res[off]);
                    v0 += rr.x; v1 += rr.y;
                }
                if (relu) { v0 = fmaxf(v0, 0.f); v1 = fmaxf(v1, 0.f); }
                *reinterpret_cast<float2*>(&C[off]) = make_float2(v0, v1);
            }
        }
    }
}

// ---------------------------------------------------------------------------
// Fused causal flash attention (fp32, online softmax). Unchanged from R2.
// ---------------------------------------------------------------------------
#define QS_STRIDE 65
#define KS_STRIDE 65
#define PS_STRIDE 68
#define VS_STRIDE 64
#define FA_SMEM_FLOATS (64 * QS_STRIDE + 64 * PS_STRIDE + 64 * VS_STRIDE)

__global__ __launch_bounds__(256) void flash_attn_kernel(
    const float* __restrict__ qkv, float* __restrict__ out)
{
    extern __shared__ float sm[];
    float* Qs = sm;
    float* U  = sm + 64 * QS_STRIDE;
    float* Vs = U + 64 * PS_STRIDE;

    int qt = blockIdx.x, bh = blockIdx.y;
    int b = bh >> 4, h = bh & 15;
    int tid = threadIdx.x;
    int tx = tid & 15;
    int ty = tid >> 4;

#pragma unroll
    for (int it = 0; it < 4; it++) {
        int idx = tid + it * 256;
        int r = idx >> 4;
        int c = (idx & 15) * 4;
        float4 v = *reinterpret_cast<const float4*>(
            &qkv[(size_t)(b * T_ + qt * 64 + r) * (3 * D_) + h * HD_ + c]);
        Qs[r * QS_STRIDE + c + 0] = v.x;
        Qs[r * QS_STRIDE + c + 1] = v.y;
        Qs[r * QS_STRIDE + c + 2] = v.z;
        Qs[r * QS_STRIDE + c + 3] = v.w;
    }

    float m[4], l[4], acc[4][4];
#pragma unroll
    for (int i = 0; i < 4; i++) {
        m[i] = -INFINITY; l[i] = 0.0f;
#pragma unroll
        for (int j = 0; j < 4; j++) acc[i][j] = 0.0f;
    }

    for (int kt = 0; kt <= qt; kt++) {
        __syncthreads();
#pragma unroll
        for (int it = 0; it < 4; it++) {
            int idx = tid + it * 256;
            int r = idx >> 4;
            int c = (idx & 15) * 4;
            size_t base = (size_t)(b * T_ + kt * 64 + r) * (3 * D_) + h * HD_ + c;
            float4 kv = *reinterpret_cast<const float4*>(&qkv[base + D_]);
            U[r * KS_STRIDE + c + 0] = kv.x;
            U[r * KS_STRIDE + c + 1] = kv.y;
            U[r * KS_STRIDE + c + 2] = kv.z;
            U[r * KS_STRIDE + c + 3] = kv.w;
            float4 vv = *reinterpret_cast<const float4*>(&qkv[base + 2 * D_]);
            *reinterpret_cast<float4*>(&Vs[r * VS_STRIDE + c]) = vv;
        }
        __syncthreads();

        float s[4][4];
#pragma unroll
        for (int i = 0; i < 4; i++)
#pragma unroll
            for (int j = 0; j < 4; j++) s[i][j] = 0.0f;
#pragma unroll 8
        for (int d = 0; d < HD_; d++) {
            float a[4], kk[4];
#pragma unroll
            for (int i = 0; i < 4; i++) a[i] = Qs[(ty * 4 + i) * QS_STRIDE + d];
#pragma unroll
            for (int j = 0; j < 4; j++) kk[j] = U[(tx * 4 + j) * KS_STRIDE + d];
#pragma unroll
            for (int i = 0; i < 4; i++)
#pragma unroll
                for (int j = 0; j < 4; j++)
                    s[i][j] = fmaf(a[i], kk[j], s[i][j]);
        }

        bool diag = (kt == qt);
#pragma unroll
        for (int i = 0; i < 4; i++)
#pragma unroll
            for (int j = 0; j < 4; j++) {
                s[i][j] *= 0.125f;
                if (diag && (tx * 4 + j > ty * 4 + i)) s[i][j] = -INFINITY;
            }

        float p[4][4];
#pragma unroll
        for (int i = 0; i < 4; i++) {
            float mt = fmaxf(fmaxf(s[i][0], s[i][1]), fmaxf(s[i][2], s[i][3]));
#pragma unroll
            for (int off = 8; off > 0; off >>= 1)
                mt = fmaxf(mt, __shfl_xor_sync(0xffffffffu, mt, off));
            float m_new = fmaxf(m[i], mt);
            float sc = expf(m[i] - m_new);
            float rs = 0.0f;
#pragma unroll
            for (int j = 0; j < 4; j++) {
                p[i][j] = expf(s[i][j] - m_new);
                rs += p[i][j];
            }
#pragma unroll
            for (int off = 8; off > 0; off >>= 1)
                rs += __shfl_xor_sync(0xffffffffu, rs, off);
            l[i] = l[i] * sc + rs;
            m[i] = m_new;
#pragma unroll
            for (int j = 0; j < 4; j++) acc[i][j] *= sc;
        }

        __syncthreads();

#pragma unroll
        for (int j = 0; j < 4; j++) {
            *reinterpret_cast<float4*>(&U[(tx * 4 + j) * PS_STRIDE + ty * 4]) =
                make_float4(p[0][j], p[1][j], p[2][j], p[3][j]);
        }
        __syncthreads();

#pragma unroll 8
        for (int k = 0; k < 64; k++) {
            float4 a4 = *reinterpret_cast<const float4*>(&U[k * PS_STRIDE + ty * 4]);
            float4 v4 = *reinterpret_cast<const float4*>(&Vs[k * VS_STRIDE + tx * 4]);
            float a[4] = {a4.x, a4.y, a4.z, a4.w};
            float v[4] = {v4.x, v4.y, v4.z, v4.w};
#pragma unroll
            for (int i = 0; i < 4; i++)
#pragma unroll
                for (int j = 0; j < 4; j++)
                    acc[i][j] = fmaf(a[i], v[j], acc[i][j]);
        }
    }

#pragma unroll
    for (int i = 0; i < 4; i++) {
        float inv = 1.0f / l[i];
        size_t off = (size_t)(b * T_ + qt * 64 + ty * 4 + i) * D_ + h * HD_ + tx * 4;
        *reinterpret_cast<float4*>(&out[off]) = make_float4(
            acc[i][0] * inv, acc[i][1] * inv, acc[i][2] * inv, acc[i][3] * inv);
    }
}

// ---------------------------------------------------------------------------
// Host launch
// ---------------------------------------------------------------------------
extern "C" void kernel_launch(void* const* d_in, const int* in_sizes, int n_in,
                              void* d_out, int out_size)
{
    const int*   idx   = (const int*)  d_in[0];
    const float* embed = (const float*)d_in[1];
    const float* Wqkv  = (const float*)d_in[2];
    const float* Wproj = (const float*)d_in[3];
    const float* bproj = (const float*)d_in[4];
    const float* ln1_g = (const float*)d_in[5];
    const float* ln1_b = (const float*)d_in[6];
    const float* ln2_g = (const float*)d_in[7];
    const float* ln2_b = (const float*)d_in[8];
    const float* W1    = (const float*)d_in[9];
    const float* b1    = (const float*)d_in[10];
    const float* W2    = (const float*)d_in[11];
    const float* b2    = (const float*)d_in[12];
    const float* lnf_g = (const float*)d_in[13];
    const float* lnf_b = (const float*)d_in[14];
    const float* Whead = (const float*)d_in[15];
    float* out = (float*)d_out;

    float *x, *xn, *qkv, *attn, *hbuf;
    cudaGetSymbolAddress((void**)&x,    g_x);
    cudaGetSymbolAddress((void**)&xn,   g_xn);
    cudaGetSymbolAddress((void**)&qkv,  g_qkv);
    cudaGetSymbolAddress((void**)&attn, g_attn);
    cudaGetSymbolAddress((void**)&hbuf, g_h);

    static int fa_smem_set = 0;
    int fa_smem_bytes = FA_SMEM_FLOATS * (int)sizeof(float);  // 50432
    if (!fa_smem_set) {
        cudaFuncSetAttribute(flash_attn_kernel,
                             cudaFuncAttributeMaxDynamicSharedMemorySize,
                             fa_smem_bytes);
        fa_smem_set = 1;
    }

    embed_kernel<<<BT_, 256>>>(idx, embed, x);

    for (int l = 0; l < L_; l++) {
        const float* wqkv_l  = Wqkv  + (size_t)l * D_ * 3 * D_;
        const float* wproj_l = Wproj + (size_t)l * D_ * D_;
        const float* bproj_l = bproj + (size_t)l * D_;
        const float* w1_l    = W1    + (size_t)l * D_ * DFF_;
        const float* b1_l    = b1    + (size_t)l * DFF_;
        const float* w2_l    = W2    + (size_t)l * DFF_ * D_;
        const float* b2_l    = b2    + (size_t)l * D_;

        layernorm_kernel<<<BT_, 256>>>(x, ln1_g + (size_t)l * D_,
                                       ln1_b + (size_t)l * D_, xn);
        sgemm_tc_kernel<<<dim3(3 * D_ / BN, BT_ / BM), 256>>>(
            xn, wqkv_l, nullptr, nullptr, qkv, BT_, 3 * D_, D_, 0);
        flash_attn_kernel<<<dim3(T_ / 64, BH_), 256, fa_smem_bytes>>>(qkv, attn);
        sgemm_tc_kernel<<<dim3(D_ / BN, BT_ / BM), 256>>>(
            attn, wproj_l, bproj_l, x, x, BT_, D_, D_, 0);
        layernorm_kernel<<<BT_, 256>>>(x, ln2_g + (size_t)l * D_,
                                       ln2_b + (size_t)l * D_, xn);
        sgemm_tc_kernel<<<dim3(DFF_ / BN, BT_ / BM), 256>>>(
            xn, w1_l, b1_l, nullptr, hbuf, BT_, DFF_, D_, 1);
        sgemm_tc_kernel<<<dim3(D_ / BN, BT_ / BM), 256>>>(
            hbuf, w2_l, b2_l, x, x, BT_, D_, DFF_, 0);
    }

    layernorm_kernel<<<BT_, 256>>>(x, lnf_g, lnf_b, xn);
    sgemm_tc_kernel<<<dim3(V_ / BN, BT_ / BM), 256>>>(
        xn, Whead, nullptr, nullptr, out, BT_, V_, D_, 0);
}

// round 4
// speedup vs baseline: 2.3099x; 1.1434x over previous
#include <cuda_runtime.h>
#include <cuda_bf16.h>
#include <math.h>
#include <stdint.h>

// ---------------------------------------------------------------------------
// Problem constants
// ---------------------------------------------------------------------------
#define B_   2
#define T_   1024
#define D_   1024
#define H_   16
#define HD_  64
#define L_   8
#define DFF_ 4096
#define V_   32000
#define BT_  (B_ * T_)          // 2048
#define BH_  (B_ * H_)          // 32
#define EPS_ 1e-5f

// ---------------------------------------------------------------------------
// Scratch (device globals; allocation-free per harness rules). 80 MB total.
// ---------------------------------------------------------------------------
__device__ float g_x[BT_ * D_];
__device__ float g_xn[BT_ * D_];
__device__ float g_qkv[BT_ * 3 * D_];
__device__ float g_attn[BT_ * D_];
__device__ float g_h[BT_ * DFF_];

// ---------------------------------------------------------------------------
// Helpers
// ---------------------------------------------------------------------------
__device__ __forceinline__ uint32_t f2tf32(float x) {
    uint32_t u;
    asm("cvt.rna.tf32.f32 %0, %1;" : "=r"(u) : "f"(x));
    return u;
}

__device__ __forceinline__ void mma_tf32(
    float& c0, float& c1, float& c2, float& c3,
    uint32_t a0, uint32_t a1, uint32_t a2, uint32_t a3,
    uint32_t b0, uint32_t b1)
{
    asm volatile(
        "mma.sync.aligned.m16n8k8.row.col.f32.tf32.tf32.f32 "
        "{%0,%1,%2,%3}, {%4,%5,%6,%7}, {%8,%9}, {%0,%1,%2,%3};"
        : "+f"(c0), "+f"(c1), "+f"(c2), "+f"(c3)
        : "r"(a0), "r"(a1), "r"(a2), "r"(a3), "r"(b0), "r"(b1));
}

// ---------------------------------------------------------------------------
// Embedding + sinusoidal positional encoding
// ---------------------------------------------------------------------------
__global__ __launch_bounds__(256) void embed_kernel(
    const int* __restrict__ idx, const float* __restrict__ embed,
    float* __restrict__ x)
{
    int bt  = blockIdx.x;
    int t   = bt % T_;
    int tok = idx[bt];
    const float neg_log_1e4_over_d = -logf(10000.0f) / (float)D_;
    int d0 = threadIdx.x * 4;
    const float* erow = embed + (size_t)tok * D_;
    float* xrow = x + (size_t)bt * D_;
    float4 e = *reinterpret_cast<const float4*>(erow + d0);
    float out[4] = {e.x, e.y, e.z, e.w};
#pragma unroll
    for (int i = 0; i < 4; i++) {
        int d = d0 + i;
        int i2 = d & ~1;
        float ang = (float)t * expf((float)i2 * neg_log_1e4_over_d);
        float pe = (d & 1) ? cosf(ang) : sinf(ang);
        out[i] += pe;
    }
    *reinterpret_cast<float4*>(xrow + d0) =
        make_float4(out[0], out[1], out[2], out[3]);
}

// ---------------------------------------------------------------------------
// LayerNorm
// ---------------------------------------------------------------------------
__global__ __launch_bounds__(256) void layernorm_kernel(
    const float* __restrict__ x, const float* __restrict__ g,
    const float* __restrict__ b, float* __restrict__ y)
{
    __shared__ float red[256];
    int row = blockIdx.x;
    int tid = threadIdx.x;
    const float* xr = x + (size_t)row * D_;
    float4 v = reinterpret_cast<const float4*>(xr)[tid];

    float s = v.x + v.y + v.z + v.w;
    red[tid] = s;
    __syncthreads();
    for (int off = 128; off > 0; off >>= 1) {
        if (tid < off) red[tid] += red[tid + off];
        __syncthreads();
    }
    float mu = red[0] * (1.0f / D_);
    __syncthreads();

    float d0 = v.x - mu, d1 = v.y - mu, d2 = v.z - mu, d3 = v.w - mu;
    red[tid] = d0 * d0 + d1 * d1 + d2 * d2 + d3 * d3;
    __syncthreads();
    for (int off = 128; off > 0; off >>= 1) {
        if (tid < off) red[tid] += red[tid + off];
        __syncthreads();
    }
    float var = red[0] * (1.0f / D_);
    float rs = rsqrtf(var + EPS_);

    float4 gg = reinterpret_cast<const float4*>(g)[tid];
    float4 bb = reinterpret_cast<const float4*>(b)[tid];
    float4 o;
    o.x = d0 * rs * gg.x + bb.x;
    o.y = d1 * rs * gg.y + bb.y;
    o.z = d2 * rs * gg.z + bb.z;
    o.w = d3 * rs * gg.w + bb.w;
    reinterpret_cast<float4*>(y + (size_t)row * D_)[tid] = o;
}

// ---------------------------------------------------------------------------
// Tensor-core SGEMM (tf32 mma.sync), double-buffered + register-prefetched.
// BM=BN=128, BK=16. 256 threads = 8 warps (2M x 4N); warp tile 64x32.
// One __syncthreads per BK tile. smem: 2-stage As/Bs (34.8 KB total).
// ---------------------------------------------------------------------------
#define BM 128
#define BN 128
#define BK 16
#define SSTR 136

__global__ __launch_bounds__(256) void sgemm_tc_kernel(
    const float* __restrict__ A, const float* __restrict__ B,
    const float* __restrict__ bias, const float* __restrict__ res,
    float* __restrict__ C, int M, int N, int K, int relu)
{
    __shared__ uint32_t As[2][BK * SSTR];
    __shared__ uint32_t Bs[2][BK * SSTR];

    int bx = blockIdx.x;
    int by = blockIdx.y;
    int tid  = threadIdx.x;
    int wid  = tid >> 5;
    int lane = tid & 31;
    int lq   = lane >> 2;
    int lr   = lane & 3;

    int warp_m = wid & 1;
    int warp_n = wid >> 1;
    int wm0 = warp_m * 64;
    int wn0 = warp_n * 32;

    // per-thread load coordinates (fixed across tiles)
    int a_r0 = tid >> 2;                 // 0..63   (A rows for it=0)
    int a_c  = (tid & 3) * 4;            // k: 0,4,8,12
    int b_r0 = tid >> 5;                 // 0..7    (B k-rows for it=0)
    int b_c  = (tid & 31) * 4;           // n: 0..124
    const float* Abase = A + (size_t)(by * BM) * K;
    const float* Bbase = B + (size_t)bx * BN;

    float4 pa[2], pb[2];

    float acc[4][4][4];
#pragma unroll
    for (int i = 0; i < 4; i++)
#pragma unroll
        for (int j = 0; j < 4; j++)
#pragma unroll
            for (int r = 0; r < 4; r++) acc[i][j][r] = 0.0f;

    // ---- prologue: load tile 0 ----
#pragma unroll
    for (int it = 0; it < 2; it++) {
        pa[it] = *reinterpret_cast<const float4*>(
            &Abase[(size_t)(a_r0 + it * 64) * K + a_c]);
        pb[it] = *reinterpret_cast<const float4*>(
            &Bbase[(size_t)(b_r0 + it * 8) * N + b_c]);
    }
#pragma unroll
    for (int it = 0; it < 2; it++) {
        int ar = a_r0 + it * 64;
        As[0][(a_c + 0) * SSTR + ar] = f2tf32(pa[it].x);
        As[0][(a_c + 1) * SSTR + ar] = f2tf32(pa[it].y);
        As[0][(a_c + 2) * SSTR + ar] = f2tf32(pa[it].z);
        As[0][(a_c + 3) * SSTR + ar] = f2tf32(pa[it].w);
        uint4 u;
        u.x = f2tf32(pb[it].x); u.y = f2tf32(pb[it].y);
        u.z = f2tf32(pb[it].z); u.w = f2tf32(pb[it].w);
        *reinterpret_cast<uint4*>(&Bs[0][(b_r0 + it * 8) * SSTR + b_c]) = u;
    }
    __syncthreads();

    int ntile = K / BK;
    for (int t = 0; t < ntile; t++) {
        int buf = t & 1;
        // ---- issue next tile's global loads early ----
        if (t + 1 < ntile) {
            int k0 = (t + 1) * BK;
#pragma unroll
            for (int it = 0; it < 2; it++) {
                pa[it] = *reinterpret_cast<const float4*>(
                    &Abase[(size_t)(a_r0 + it * 64) * K + k0 + a_c]);
                pb[it] = *reinterpret_cast<const float4*>(
                    &Bbase[(size_t)(k0 + b_r0 + it * 8) * N + b_c]);
            }
        }

        // ---- compute current tile ----
#pragma unroll
        for (int ks = 0; ks < BK; ks += 8) {
            uint32_t af[4][4], bf[4][2];
#pragma unroll
            for (int i = 0; i < 4; i++) {
                int m = wm0 + i * 16 + lq;
                af[i][0] = As[buf][(ks + lr)     * SSTR + m];
                af[i][1] = As[buf][(ks + lr)     * SSTR + m + 8];
                af[i][2] = As[buf][(ks + lr + 4) * SSTR + m];
                af[i][3] = As[buf][(ks + lr + 4) * SSTR + m + 8];
            }
#pragma unroll
            for (int j = 0; j < 4; j++) {
                int n = wn0 + j * 8 + lq;
                bf[j][0] = Bs[buf][(ks + lr)     * SSTR + n];
                bf[j][1] = Bs[buf][(ks + lr + 4) * SSTR + n];
            }
#pragma unroll
            for (int i = 0; i < 4; i++)
#pragma unroll
                for (int j = 0; j < 4; j++)
                    mma_tf32(acc[i][j][0], acc[i][j][1],
                             acc[i][j][2], acc[i][j][3],
                             af[i][0], af[i][1], af[i][2], af[i][3],
                             bf[j][0], bf[j][1]);
        }

        // ---- store next tile into alternate buffer ----
        if (t + 1 < ntile) {
            int nb = 1 - buf;
#pragma unroll
            for (int it = 0; it < 2; it++) {
                int ar = a_r0 + it * 64;
                As[nb][(a_c + 0) * SSTR + ar] = f2tf32(pa[it].x);
                As[nb][(a_c + 1) * SSTR + ar] = f2tf32(pa[it].y);
                As[nb][(a_c + 2) * SSTR + ar] = f2tf32(pa[it].z);
                As[nb][(a_c + 3) * SSTR + ar] = f2tf32(pa[it].w);
                uint4 u;
                u.x = f2tf32(pb[it].x); u.y = f2tf32(pb[it].y);
                u.z = f2tf32(pb[it].z); u.w = f2tf32(pb[it].w);
                *reinterpret_cast<uint4*>(&Bs[nb][(b_r0 + it * 8) * SSTR + b_c]) = u;
            }
            __syncthreads();
        }
    }

    // ---- epilogue ----
    int rowbase = by * BM + wm0;
    int colbase = bx * BN + wn0;
#pragma unroll
    for (int i = 0; i < 4; i++) {
#pragma unroll
        for (int j = 0; j < 4; j++) {
            int col = colbase + j * 8 + lr * 2;
#pragma unroll
            for (int half = 0; half < 2; half++) {
                int row = rowbase + i * 16 + lq + half * 8;
                size_t off = (size_t)row * N + col;
                float v0 = acc[i][j][half * 2 + 0];
                float v1 = acc[i][j][half * 2 + 1];
                if (bias) {
                    float2 bs = *reinterpret_cast<const float2*>(&bias[col]);
                    v0 += bs.x; v1 += bs.y;
                }
                if (res) {
                    float2 rr = *reinterpret_cast<const float2*>(&res[off]);
                    v0 += rr.x; v1 += rr.y;
                }
                if (relu) { v0 = fmaxf(v0, 0.f); v1 = fmaxf(v1, 0.f); }
                *reinterpret_cast<float2*>(&C[off]) = make_float2(v0, v1);
            }
        }
    }
}

// ---------------------------------------------------------------------------
// Fused causal flash attention (fp32, online softmax). Unchanged.
// ---------------------------------------------------------------------------
#define QS_STRIDE 65
#define KS_STRIDE 65
#define PS_STRIDE 68
#define VS_STRIDE 64
#define FA_SMEM_FLOATS (64 * QS_STRIDE + 64 * PS_STRIDE + 64 * VS_STRIDE)

__global__ __launch_bounds__(256) void flash_attn_kernel(
    const float* __restrict__ qkv, float* __restrict__ out)
{
    extern __shared__ float sm[];
    float* Qs = sm;
    float* U  = sm + 64 * QS_STRIDE;
    float* Vs = U + 64 * PS_STRIDE;

    int qt = blockIdx.x, bh = blockIdx.y;
    int b = bh >> 4, h = bh & 15;
    int tid = threadIdx.x;
    int tx = tid & 15;
    int ty = tid >> 4;

#pragma unroll
    for (int it = 0; it < 4; it++) {
        int idx = tid + it * 256;
        int r = idx >> 4;
        int c = (idx & 15) * 4;
        float4 v = *reinterpret_cast<const float4*>(
            &qkv[(size_t)(b * T_ + qt * 64 + r) * (3 * D_) + h * HD_ + c]);
        Qs[r * QS_STRIDE + c + 0] = v.x;
        Qs[r * QS_STRIDE + c + 1] = v.y;
        Qs[r * QS_STRIDE + c + 2] = v.z;
        Qs[r * QS_STRIDE + c + 3] = v.w;
    }

    float m[4], l[4], acc[4][4];
#pragma unroll
    for (int i = 0; i < 4; i++) {
        m[i] = -INFINITY; l[i] = 0.0f;
#pragma unroll
        for (int j = 0; j < 4; j++) acc[i][j] = 0.0f;
    }

    for (int kt = 0; kt <= qt; kt++) {
        __syncthreads();
#pragma unroll
        for (int it = 0; it < 4; it++) {
            int idx = tid + it * 256;
            int r = idx >> 4;
            int c = (idx & 15) * 4;
            size_t base = (size_t)(b * T_ + kt * 64 + r) * (3 * D_) + h * HD_ + c;
            float4 kv = *reinterpret_cast<const float4*>(&qkv[base + D_]);
            U[r * KS_STRIDE + c + 0] = kv.x;
            U[r * KS_STRIDE + c + 1] = kv.y;
            U[r * KS_STRIDE + c + 2] = kv.z;
            U[r * KS_STRIDE + c + 3] = kv.w;
            float4 vv = *reinterpret_cast<const float4*>(&qkv[base + 2 * D_]);
            *reinterpret_cast<float4*>(&Vs[r * VS_STRIDE + c]) = vv;
        }
        __syncthreads();

        float s[4][4];
#pragma unroll
        for (int i = 0; i < 4; i++)
#pragma unroll
            for (int j = 0; j < 4; j++) s[i][j] = 0.0f;
#pragma unroll 8
        for (int d = 0; d < HD_; d++) {
            float a[4], kk[4];
#pragma unroll
            for (int i = 0; i < 4; i++) a[i] = Qs[(ty * 4 + i) * QS_STRIDE + d];
#pragma unroll
            for (int j = 0; j < 4; j++) kk[j] = U[(tx * 4 + j) * KS_STRIDE + d];
#pragma unroll
            for (int i = 0; i < 4; i++)
#pragma unroll
                for (int j = 0; j < 4; j++)
                    s[i][j] = fmaf(a[i], kk[j], s[i][j]);
        }

        bool diag = (kt == qt);
#pragma unroll
        for (int i = 0; i < 4; i++)
#pragma unroll
            for (int j = 0; j < 4; j++) {
                s[i][j] *= 0.125f;
                if (diag && (tx * 4 + j > ty * 4 + i)) s[i][j] = -INFINITY;
            }

        float p[4][4];
#pragma unroll
        for (int i = 0; i < 4; i++) {
            float mt = fmaxf(fmaxf(s[i][0], s[i][1]), fmaxf(s[i][2], s[i][3]));
#pragma unroll
            for (int off = 8; off > 0; off >>= 1)
                mt = fmaxf(mt, __shfl_xor_sync(0xffffffffu, mt, off));
            float m_new = fmaxf(m[i], mt);
            float sc = expf(m[i] - m_new);
            float rs = 0.0f;
#pragma unroll
            for (int j = 0; j < 4; j++) {
                p[i][j] = expf(s[i][j] - m_new);
                rs += p[i][j];
            }
#pragma unroll
            for (int off = 8; off > 0; off >>= 1)
                rs += __shfl_xor_sync(0xffffffffu, rs, off);
            l[i] = l[i] * sc + rs;
            m[i] = m_new;
#pragma unroll
            for (int j = 0; j < 4; j++) acc[i][j] *= sc;
        }

        __syncthreads();

#pragma unroll
        for (int j = 0; j < 4; j++) {
            *reinterpret_cast<float4*>(&U[(tx * 4 + j) * PS_STRIDE + ty * 4]) =
                make_float4(p[0][j], p[1][j], p[2][j], p[3][j]);
        }
        __syncthreads();

#pragma unroll 8
        for (int k = 0; k < 64; k++) {
            float4 a4 = *reinterpret_cast<const float4*>(&U[k * PS_STRIDE + ty * 4]);
            float4 v4 = *reinterpret_cast<const float4*>(&Vs[k * VS_STRIDE + tx * 4]);
            float a[4] = {a4.x, a4.y, a4.z, a4.w};
            float v[4] = {v4.x, v4.y, v4.z, v4.w};
#pragma unroll
            for (int i = 0; i < 4; i++)
#pragma unroll
                for (int j = 0; j < 4; j++)
                    acc[i][j] = fmaf(a[i], v[j], acc[i][j]);
        }
    }

#pragma unroll
    for (int i = 0; i < 4; i++) {
        float inv = 1.0f / l[i];
        size_t off = (size_t)(b * T_ + qt * 64 + ty * 4 + i) * D_ + h * HD_ + tx * 4;
        *reinterpret_cast<float4*>(&out[off]) = make_float4(
            acc[i][0] * inv, acc[i][1] * inv, acc[i][2] * inv, acc[i][3] * inv);
    }
}

// ---------------------------------------------------------------------------
// Host launch
// ---------------------------------------------------------------------------
extern "C" void kernel_launch(void* const* d_in, const int* in_sizes, int n_in,
                              void* d_out, int out_size)
{
    const int*   idx   = (const int*)  d_in[0];
    const float* embed = (const float*)d_in[1];
    const float* Wqkv  = (const float*)d_in[2];
    const float* Wproj = (const float*)d_in[3];
    const float* bproj = (const float*)d_in[4];
    const float* ln1_g = (const float*)d_in[5];
    const float* ln1_b = (const float*)d_in[6];
    const float* ln2_g = (const float*)d_in[7];
    const float* ln2_b = (const float*)d_in[8];
    const float* W1    = (const float*)d_in[9];
    const float* b1    = (const float*)d_in[10];
    const float* W2    = (const float*)d_in[11];
    const float* b2    = (const float*)d_in[12];
    const float* lnf_g = (const float*)d_in[13];
    const float* lnf_b = (const float*)d_in[14];
    const float* Whead = (const float*)d_in[15];
    float* out = (float*)d_out;

    float *x, *xn, *qkv, *attn, *hbuf;
    cudaGetSymbolAddress((void**)&x,    g_x);
    cudaGetSymbolAddress((void**)&xn,   g_xn);
    cudaGetSymbolAddress((void**)&qkv,  g_qkv);
    cudaGetSymbolAddress((void**)&attn, g_attn);
    cudaGetSymbolAddress((void**)&hbuf, g_h);

    int fa_smem_bytes = FA_SMEM_FLOATS * (int)sizeof(float);  // 50432
    cudaFuncSetAttribute(flash_attn_kernel,
                         cudaFuncAttributeMaxDynamicSharedMemorySize,
                         fa_smem_bytes);

    embed_kernel<<<BT_, 256>>>(idx, embed, x);

    for (int l = 0; l < L_; l++) {
        const float* wqkv_l  = Wqkv  + (size_t)l * D_ * 3 * D_;
        const float* wproj_l = Wproj + (size_t)l * D_ * D_;
        const float* bproj_l = bproj + (size_t)l * D_;
        const float* w1_l    = W1    + (size_t)l * D_ * DFF_;
        const float* b1_l    = b1    + (size_t)l * DFF_;
        const float* w2_l    = W2    + (size_t)l * DFF_ * D_;
        const float* b2_l    = b2    + (size_t)l * D_;

        layernorm_kernel<<<BT_, 256>>>(x, ln1_g + (size_t)l * D_,
                                       ln1_b + (size_t)l * D_, xn);
        sgemm_tc_kernel<<<dim3(3 * D_ / BN, BT_ / BM), 256>>>(
            xn, wqkv_l, nullptr, nullptr, qkv, BT_, 3 * D_, D_, 0);
        flash_attn_kernel<<<dim3(T_ / 64, BH_), 256, fa_smem_bytes>>>(qkv, attn);
        sgemm_tc_kernel<<<dim3(D_ / BN, BT_ / BM), 256>>>(
            attn, wproj_l, bproj_l, x, x, BT_, D_, D_, 0);
        layernorm_kernel<<<BT_, 256>>>(x, ln2_g + (size_t)l * D_,
                                       ln2_b + (size_t)l * D_, xn);
        sgemm_tc_kernel<<<dim3(DFF_ / BN, BT_ / BM), 256>>>(
            xn, w1_l, b1_l, nullptr, hbuf, BT_, DFF_, D_, 1);
        sgemm_tc_kernel<<<dim3(D_ / BN, BT_ / BM), 256>>>(
            hbuf, w2_l, b2_l, x, x, BT_, D_, DFF_, 0);
    }

    layernorm_kernel<<<BT_, 256>>>(x, lnf_g, lnf_b, xn);
    sgemm_tc_kernel<<<dim3(V_ / BN, BT_ / BM), 256>>>(
        xn, Whead, nullptr, nullptr, out, BT_, V_, D_, 0);
}

// round 5
// speedup vs baseline: 2.6494x; 1.1470x over previous
#include <cuda_runtime.h>
#include <cuda_bf16.h>
#include <math.h>
#include <stdint.h>

// ---------------------------------------------------------------------------
// Problem constants
// ---------------------------------------------------------------------------
#define B_   2
#define T_   1024
#define D_   1024
#define H_   16
#define HD_  64
#define L_   8
#define DFF_ 4096
#define V_   32000
#define BT_  (B_ * T_)          // 2048
#define BH_  (B_ * H_)          // 32
#define EPS_ 1e-5f

// ---------------------------------------------------------------------------
// Scratch (device globals; allocation-free per harness rules). ~614 MB.
// ---------------------------------------------------------------------------
__device__ float g_x[BT_ * D_];
__device__ float g_xn[BT_ * D_];
__device__ float g_qkv[BT_ * 3 * D_];
__device__ float g_attn[BT_ * D_];
__device__ float g_h[BT_ * DFF_];
// tf32-rounded weight copies
__device__ float g_wqkv_t[L_ * D_ * 3 * D_];
__device__ float g_wproj_t[L_ * D_ * D_];
__device__ float g_w1_t[L_ * D_ * DFF_];
__device__ float g_w2_t[L_ * DFF_ * D_];
__device__ float g_whead_t[D_ * V_];

// ---------------------------------------------------------------------------
// Helpers
// ---------------------------------------------------------------------------
__device__ __forceinline__ uint32_t f2tf32(float x) {
    uint32_t u;
    asm("cvt.rna.tf32.f32 %0, %1;" : "=r"(u) : "f"(x));
    return u;
}
__device__ __forceinline__ float round_tf32(float x) {
    return __uint_as_float(f2tf32(x));
}

__device__ __forceinline__ void mma_tf32(
    float& c0, float& c1, float& c2, float& c3,
    uint32_t a0, uint32_t a1, uint32_t a2, uint32_t a3,
    uint32_t b0, uint32_t b1)
{
    asm volatile(
        "mma.sync.aligned.m16n8k8.row.col.f32.tf32.tf32.f32 "
        "{%0,%1,%2,%3}, {%4,%5,%6,%7}, {%8,%9}, {%0,%1,%2,%3};"
        : "+f"(c0), "+f"(c1), "+f"(c2), "+f"(c3)
        : "r"(a0), "r"(a1), "r"(a2), "r"(a3), "r"(b0), "r"(b1));
}

__device__ __forceinline__ void cp_async16(uint32_t smem_dst, const void* gptr) {
    asm volatile("cp.async.cg.shared.global [%0], [%1], 16;"
                 :: "r"(smem_dst), "l"(gptr));
}
__device__ __forceinline__ void cp_commit() {
    asm volatile("cp.async.commit_group;");
}
template <int N>
__device__ __forceinline__ void cp_wait() {
    asm volatile("cp.async.wait_group %0;" :: "n"(N));
}

// ---------------------------------------------------------------------------
// Weight pre-round: out[i] = tf32_rna(in[i]) as fp32
// ---------------------------------------------------------------------------
__global__ __launch_bounds__(256) void round_weights_kernel(
    const float4* __restrict__ in, float4* __restrict__ out, int n4)
{
    int stride = gridDim.x * blockDim.x;
    for (int i = blockIdx.x * blockDim.x + threadIdx.x; i < n4; i += stride) {
        float4 v = in[i];
        v.x = round_tf32(v.x); v.y = round_tf32(v.y);
        v.z = round_tf32(v.z); v.w = round_tf32(v.w);
        out[i] = v;
    }
}

// ---------------------------------------------------------------------------
// Embedding + sinusoidal positional encoding
// ---------------------------------------------------------------------------
__global__ __launch_bounds__(256) void embed_kernel(
    const int* __restrict__ idx, const float* __restrict__ embed,
    float* __restrict__ x)
{
    int bt  = blockIdx.x;
    int t   = bt % T_;
    int tok = idx[bt];
    const float neg_log_1e4_over_d = -logf(10000.0f) / (float)D_;
    int d0 = threadIdx.x * 4;
    const float* erow = embed + (size_t)tok * D_;
    float* xrow = x + (size_t)bt * D_;
    float4 e = *reinterpret_cast<const float4*>(erow + d0);
    float out[4] = {e.x, e.y, e.z, e.w};
#pragma unroll
    for (int i = 0; i < 4; i++) {
        int d = d0 + i;
        int i2 = d & ~1;
        float ang = (float)t * expf((float)i2 * neg_log_1e4_over_d);
        float pe = (d & 1) ? cosf(ang) : sinf(ang);
        out[i] += pe;
    }
    *reinterpret_cast<float4*>(xrow + d0) =
        make_float4(out[0], out[1], out[2], out[3]);
}

// ---------------------------------------------------------------------------
// LayerNorm; output rounded to tf32 grid (feeds GEMM A operand).
// ---------------------------------------------------------------------------
__global__ __launch_bounds__(256) void layernorm_kernel(
    const float* __restrict__ x, const float* __restrict__ g,
    const float* __restrict__ b, float* __restrict__ y)
{
    __shared__ float red[256];
    int row = blockIdx.x;
    int tid = threadIdx.x;
    const float* xr = x + (size_t)row * D_;
    float4 v = reinterpret_cast<const float4*>(xr)[tid];

    float s = v.x + v.y + v.z + v.w;
    red[tid] = s;
    __syncthreads();
    for (int off = 128; off > 0; off >>= 1) {
        if (tid < off) red[tid] += red[tid + off];
        __syncthreads();
    }
    float mu = red[0] * (1.0f / D_);
    __syncthreads();

    float d0 = v.x - mu, d1 = v.y - mu, d2 = v.z - mu, d3 = v.w - mu;
    red[tid] = d0 * d0 + d1 * d1 + d2 * d2 + d3 * d3;
    __syncthreads();
    for (int off = 128; off > 0; off >>= 1) {
        if (tid < off) red[tid] += red[tid + off];
        __syncthreads();
    }
    float var = red[0] * (1.0f / D_);
    float rs = rsqrtf(var + EPS_);

    float4 gg = reinterpret_cast<const float4*>(g)[tid];
    float4 bb = reinterpret_cast<const float4*>(b)[tid];
    float4 o;
    o.x = round_tf32(d0 * rs * gg.x + bb.x);
    o.y = round_tf32(d1 * rs * gg.y + bb.y);
    o.z = round_tf32(d2 * rs * gg.z + bb.z);
    o.w = round_tf32(d3 * rs * gg.w + bb.w);
    reinterpret_cast<float4*>(y + (size_t)row * D_)[tid] = o;
}

// ---------------------------------------------------------------------------
// Tensor-core SGEMM (tf32 mma.sync), 4-stage cp.async pipeline.
// Inputs MUST already be tf32-rounded fp32 (no conversion in mainloop).
// BM=BN=128, BK=16. 256 threads = 8 warps (2M x 4N); warp tile 64x32.
// smem/stage: A[m][k] stride 20 words (2560 w) + B[k][n] stride 136 (2176 w).
// flags: bit0 = relu, bit1 = round output to tf32 grid.
// ---------------------------------------------------------------------------
#define BM 128
#define BN 128
#define BK 16
#define AW 20                 // A row stride in words
#define BW 136                // B row stride in words
#define AWORDS (128 * AW)     // 2560
#define STW (AWORDS + 16 * BW) // 4736 words per stage
#define NSTAGE 4
#define SGEMM_SMEM_BYTES (NSTAGE * STW * 4)   // 75776

__global__ __launch_bounds__(256) void sgemm_tc_kernel(
    const float* __restrict__ A, const float* __restrict__ B,
    const float* __restrict__ bias, const float* __restrict__ res,
    float* __restrict__ C, int M, int N, int K, int flags)
{
    extern __shared__ float smem[];
    uint32_t smem_u32 = (uint32_t)__cvta_generic_to_shared(smem);

    int bx = blockIdx.x;
    int by = blockIdx.y;
    int tid  = threadIdx.x;
    int wid  = tid >> 5;
    int lane = tid & 31;
    int lq   = lane >> 2;
    int lr   = lane & 3;

    int wm0 = (wid & 1) * 64;
    int wn0 = (wid >> 1) * 32;

    // per-thread cp.async coordinates
    int a_r0 = tid >> 2;                 // 0..63 (and +64)
    int a_c  = (tid & 3) * 4;            // k word 0,4,8,12
    int b_r0 = tid >> 5;                 // 0..7  (and +8)
    int b_c  = (tid & 31) * 4;           // n word 0..124
    const float* Abase = A + (size_t)(by * BM) * K;
    const float* Bbase = B + (size_t)bx * BN;

    float acc[4][4][4];
#pragma unroll
    for (int i = 0; i < 4; i++)
#pragma unroll
        for (int j = 0; j < 4; j++)
#pragma unroll
            for (int r = 0; r < 4; r++) acc[i][j][r] = 0.0f;

    int ntile = K / BK;

    // ---- issue loads for one stage ----
    auto issue = [&](int t) {
        int st = t & (NSTAGE - 1);
        uint32_t sb = smem_u32 + st * STW * 4;
        int k0 = t * BK;
#pragma unroll
        for (int it = 0; it < 2; it++) {
            int ar = a_r0 + it * 64;
            cp_async16(sb + (ar * AW + a_c) * 4,
                       Abase + (size_t)ar * K + k0 + a_c);
            int br = b_r0 + it * 8;
            cp_async16(sb + (AWORDS + br * BW + b_c) * 4,
                       Bbase + (size_t)(k0 + br) * N + b_c);
        }
    };

    // ---- prologue: stages 0..NSTAGE-2 ----
#pragma unroll
    for (int s = 0; s < NSTAGE - 1; s++) {
        if (s < ntile) issue(s);
        cp_commit();
    }
    cp_wait<NSTAGE - 2>();
    __syncthreads();

    for (int t = 0; t < ntile; t++) {
        int st = t & (NSTAGE - 1);
        const float* sA = smem + st * STW;
        const float* sB = sA + AWORDS;

        if (t + NSTAGE - 1 < ntile) issue(t + NSTAGE - 1);
        cp_commit();

#pragma unroll
        for (int ks = 0; ks < BK; ks += 8) {
            uint32_t af[4][4], bf[4][2];
#pragma unroll
            for (int i = 0; i < 4; i++) {
                int m = wm0 + i * 16 + lq;
                af[i][0] = __float_as_uint(sA[m * AW + ks + lr]);
                af[i][1] = __float_as_uint(sA[(m + 8) * AW + ks + lr]);
                af[i][2] = __float_as_uint(sA[m * AW + ks + lr + 4]);
                af[i][3] = __float_as_uint(sA[(m + 8) * AW + ks + lr + 4]);
            }
#pragma unroll
            for (int j = 0; j < 4; j++) {
                int n = wn0 + j * 8 + lq;
                bf[j][0] = __float_as_uint(sB[(ks + lr) * BW + n]);
                bf[j][1] = __float_as_uint(sB[(ks + lr + 4) * BW + n]);
            }
#pragma unroll
            for (int i = 0; i < 4; i++)
#pragma unroll
                for (int j = 0; j < 4; j++)
                    mma_tf32(acc[i][j][0], acc[i][j][1],
                             acc[i][j][2], acc[i][j][3],
                             af[i][0], af[i][1], af[i][2], af[i][3],
                             bf[j][0], bf[j][1]);
        }

        cp_wait<NSTAGE - 2>();
        __syncthreads();
    }

    // ---- epilogue ----
    int relu  = flags & 1;
    int rnd   = flags & 2;
    int rowbase = by * BM + wm0;
    int colbase = bx * BN + wn0;
#pragma unroll
    for (int i = 0; i < 4; i++) {
#pragma unroll
        for (int j = 0; j < 4; j++) {
            int col = colbase + j * 8 + lr * 2;
#pragma unroll
            for (int half = 0; half < 2; half++) {
                int row = rowbase + i * 16 + lq + half * 8;
                size_t off = (size_t)row * N + col;
                float v0 = acc[i][j][half * 2 + 0];
                float v1 = acc[i][j][half * 2 + 1];
                if (bias) {
                    float2 bs = *reinterpret_cast<const float2*>(&bias[col]);
                    v0 += bs.x; v1 += bs.y;
                }
                if (res) {
                    float2 rr = *reinterpret_cast<const float2*>(&res[off]);
                    v0 += rr.x; v1 += rr.y;
                }
                if (relu) { v0 = fmaxf(v0, 0.f); v1 = fmaxf(v1, 0.f); }
                if (rnd)  { v0 = round_tf32(v0); v1 = round_tf32(v1); }
                *reinterpret_cast<float2*>(&C[off]) = make_float2(v0, v1);
            }
        }
    }
}

// ---------------------------------------------------------------------------
// Fused causal flash attention (fp32, online softmax).
// Output rounded to tf32 grid (feeds proj GEMM A operand).
// ---------------------------------------------------------------------------
#define QS_STRIDE 65
#define KS_STRIDE 65
#define PS_STRIDE 68
#define VS_STRIDE 64
#define FA_SMEM_FLOATS (64 * QS_STRIDE + 64 * PS_STRIDE + 64 * VS_STRIDE)

__global__ __launch_bounds__(256) void flash_attn_kernel(
    const float* __restrict__ qkv, float* __restrict__ out)
{
    extern __shared__ float sm[];
    float* Qs = sm;
    float* U  = sm + 64 * QS_STRIDE;
    float* Vs = U + 64 * PS_STRIDE;

    int qt = blockIdx.x, bh = blockIdx.y;
    int b = bh >> 4, h = bh & 15;
    int tid = threadIdx.x;
    int tx = tid & 15;
    int ty = tid >> 4;

#pragma unroll
    for (int it = 0; it < 4; it++) {
        int idx = tid + it * 256;
        int r = idx >> 4;
        int c = (idx & 15) * 4;
        float4 v = *reinterpret_cast<const float4*>(
            &qkv[(size_t)(b * T_ + qt * 64 + r) * (3 * D_) + h * HD_ + c]);
        Qs[r * QS_STRIDE + c + 0] = v.x;
        Qs[r * QS_STRIDE + c + 1] = v.y;
        Qs[r * QS_STRIDE + c + 2] = v.z;
        Qs[r * QS_STRIDE + c + 3] = v.w;
    }

    float m[4], l[4], acc[4][4];
#pragma unroll
    for (int i = 0; i < 4; i++) {
        m[i] = -INFINITY; l[i] = 0.0f;
#pragma unroll
        for (int j = 0; j < 4; j++) acc[i][j] = 0.0f;
    }

    for (int kt = 0; kt <= qt; kt++) {
        __syncthreads();
#pragma unroll
        for (int it = 0; it < 4; it++) {
            int idx = tid + it * 256;
            int r = idx >> 4;
            int c = (idx & 15) * 4;
            size_t base = (size_t)(b * T_ + kt * 64 + r) * (3 * D_) + h * HD_ + c;
            float4 kv = *reinterpret_cast<const float4*>(&qkv[base + D_]);
            U[r * KS_STRIDE + c + 0] = kv.x;
            U[r * KS_STRIDE + c + 1] = kv.y;
            U[r * KS_STRIDE + c + 2] = kv.z;
            U[r * KS_STRIDE + c + 3] = kv.w;
            float4 vv = *reinterpret_cast<const float4*>(&qkv[base + 2 * D_]);
            *reinterpret_cast<float4*>(&Vs[r * VS_STRIDE + c]) = vv;
        }
        __syncthreads();

        float s[4][4];
#pragma unroll
        for (int i = 0; i < 4; i++)
#pragma unroll
            for (int j = 0; j < 4; j++) s[i][j] = 0.0f;
#pragma unroll 8
        for (int d = 0; d < HD_; d++) {
            float a[4], kk[4];
#pragma unroll
            for (int i = 0; i < 4; i++) a[i] = Qs[(ty * 4 + i) * QS_STRIDE + d];
#pragma unroll
            for (int j = 0; j < 4; j++) kk[j] = U[(tx * 4 + j) * KS_STRIDE + d];
#pragma unroll
            for (int i = 0; i < 4; i++)
#pragma unroll
                for (int j = 0; j < 4; j++)
                    s[i][j] = fmaf(a[i], kk[j], s[i][j]);
        }

        bool diag = (kt == qt);
#pragma unroll
        for (int i = 0; i < 4; i++)
#pragma unroll
            for (int j = 0; j < 4; j++) {
                s[i][j] *= 0.125f;
                if (diag && (tx * 4 + j > ty * 4 + i)) s[i][j] = -INFINITY;
            }

        float p[4][4];
#pragma unroll
        for (int i = 0; i < 4; i++) {
            float mt = fmaxf(fmaxf(s[i][0], s[i][1]), fmaxf(s[i][2], s[i][3]));
#pragma unroll
            for (int off = 8; off > 0; off >>= 1)
                mt = fmaxf(mt, __shfl_xor_sync(0xffffffffu, mt, off));
            float m_new = fmaxf(m[i], mt);
            float sc = expf(m[i] - m_new);
            float rs = 0.0f;
#pragma unroll
            for (int j = 0; j < 4; j++) {
                p[i][j] = expf(s[i][j] - m_new);
                rs += p[i][j];
            }
#pragma unroll
            for (int off = 8; off > 0; off >>= 1)
                rs += __shfl_xor_sync(0xffffffffu, rs, off);
            l[i] = l[i] * sc + rs;
            m[i] = m_new;
#pragma unroll
            for (int j = 0; j < 4; j++) acc[i][j] *= sc;
        }

        __syncthreads();

#pragma unroll
        for (int j = 0; j < 4; j++) {
            *reinterpret_cast<float4*>(&U[(tx * 4 + j) * PS_STRIDE + ty * 4]) =
                make_float4(p[0][j], p[1][j], p[2][j], p[3][j]);
        }
        __syncthreads();

#pragma unroll 8
        for (int k = 0; k < 64; k++) {
            float4 a4 = *reinterpret_cast<const float4*>(&U[k * PS_STRIDE + ty * 4]);
            float4 v4 = *reinterpret_cast<const float4*>(&Vs[k * VS_STRIDE + tx * 4]);
            float a[4] = {a4.x, a4.y, a4.z, a4.w};
            float v[4] = {v4.x, v4.y, v4.z, v4.w};
#pragma unroll
            for (int i = 0; i < 4; i++)
#pragma unroll
                for (int j = 0; j < 4; j++)
                    acc[i][j] = fmaf(a[i], v[j], acc[i][j]);
        }
    }

#pragma unroll
    for (int i = 0; i < 4; i++) {
        float inv = 1.0f / l[i];
        size_t off = (size_t)(b * T_ + qt * 64 + ty * 4 + i) * D_ + h * HD_ + tx * 4;
        *reinterpret_cast<float4*>(&out[off]) = make_float4(
            round_tf32(acc[i][0] * inv), round_tf32(acc[i][1] * inv),
            round_tf32(acc[i][2] * inv), round_tf32(acc[i][3] * inv));
    }
}

// ---------------------------------------------------------------------------
// Host launch
// ---------------------------------------------------------------------------
extern "C" void kernel_launch(void* const* d_in, const int* in_sizes, int n_in,
                              void* d_out, int out_size)
{
    const int*   idx   = (const int*)  d_in[0];
    const float* embed = (const float*)d_in[1];
    const float* Wqkv  = (const float*)d_in[2];
    const float* Wproj = (const float*)d_in[3];
    const float* bproj = (const float*)d_in[4];
    const float* ln1_g = (const float*)d_in[5];
    const float* ln1_b = (const float*)d_in[6];
    const float* ln2_g = (const float*)d_in[7];
    const float* ln2_b = (const float*)d_in[8];
    const float* W1    = (const float*)d_in[9];
    const float* b1    = (const float*)d_in[10];
    const float* W2    = (const float*)d_in[11];
    const float* b2    = (const float*)d_in[12];
    const float* lnf_g = (const float*)d_in[13];
    const float* lnf_b = (const float*)d_in[14];
    const float* Whead = (const float*)d_in[15];
    float* out = (float*)d_out;

    float *x, *xn, *qkv, *attn, *hbuf;
    float *wqkv_t, *wproj_t, *w1_t, *w2_t, *whead_t;
    cudaGetSymbolAddress((void**)&x,    g_x);
    cudaGetSymbolAddress((void**)&xn,   g_xn);
    cudaGetSymbolAddress((void**)&qkv,  g_qkv);
    cudaGetSymbolAddress((void**)&attn, g_attn);
    cudaGetSymbolAddress((void**)&hbuf, g_h);
    cudaGetSymbolAddress((void**)&wqkv_t,  g_wqkv_t);
    cudaGetSymbolAddress((void**)&wproj_t, g_wproj_t);
    cudaGetSymbolAddress((void**)&w1_t,    g_w1_t);
    cudaGetSymbolAddress((void**)&w2_t,    g_w2_t);
    cudaGetSymbolAddress((void**)&whead_t, g_whead_t);

    int fa_smem_bytes = FA_SMEM_FLOATS * (int)sizeof(float);  // 50432
    cudaFuncSetAttribute(flash_attn_kernel,
                         cudaFuncAttributeMaxDynamicSharedMemorySize,
                         fa_smem_bytes);
    cudaFuncSetAttribute(sgemm_tc_kernel,
                         cudaFuncAttributeMaxDynamicSharedMemorySize,
                         SGEMM_SMEM_BYTES);

    // ---- pre-round weights to tf32 grid ----
    {
        struct { const float* src; float* dst; int n; } jobs[5] = {
            {Wqkv,  wqkv_t,  L_ * D_ * 3 * D_},
            {Wproj, wproj_t, L_ * D_ * D_},
            {W1,    w1_t,    L_ * D_ * DFF_},
            {W2,    w2_t,    L_ * DFF_ * D_},
            {Whead, whead_t, D_ * V_},
        };
        for (int j = 0; j < 5; j++) {
            int n4 = jobs[j].n / 4;
            int blocks = (n4 + 255) / 256;
            if (blocks > 16384) blocks = 16384;
            round_weights_kernel<<<blocks, 256>>>(
                (const float4*)jobs[j].src, (float4*)jobs[j].dst, n4);
        }
    }

    embed_kernel<<<BT_, 256>>>(idx, embed, x);

    for (int l = 0; l < L_; l++) {
        const float* wqkv_l  = wqkv_t  + (size_t)l * D_ * 3 * D_;
        const float* wproj_l = wproj_t + (size_t)l * D_ * D_;
        const float* bproj_l = bproj   + (size_t)l * D_;
        const float* w1_l    = w1_t    + (size_t)l * D_ * DFF_;
        const float* b1_l    = b1      + (size_t)l * DFF_;
        const float* w2_l    = w2_t    + (size_t)l * DFF_ * D_;
        const float* b2_l    = b2      + (size_t)l * D_;

        layernorm_kernel<<<BT_, 256>>>(x, ln1_g + (size_t)l * D_,
                                       ln1_b + (size_t)l * D_, xn);
        sgemm_tc_kernel<<<dim3(3 * D_ / BN, BT_ / BM), 256, SGEMM_SMEM_BYTES>>>(
            xn, wqkv_l, nullptr, nullptr, qkv, BT_, 3 * D_, D_, 0);
        flash_attn_kernel<<<dim3(T_ / 64, BH_), 256, fa_smem_bytes>>>(qkv, attn);
        sgemm_tc_kernel<<<dim3(D_ / BN, BT_ / BM), 256, SGEMM_SMEM_BYTES>>>(
            attn, wproj_l, bproj_l, x, x, BT_, D_, D_, 0);
        layernorm_kernel<<<BT_, 256>>>(x, ln2_g + (size_t)l * D_,
                                       ln2_b + (size_t)l * D_, xn);
        sgemm_tc_kernel<<<dim3(DFF_ / BN, BT_ / BM), 256, SGEMM_SMEM_BYTES>>>(
            xn, w1_l, b1_l, nullptr, hbuf, BT_, DFF_, D_, 1 | 2);
        sgemm_tc_kernel<<<dim3(D_ / BN, BT_ / BM), 256, SGEMM_SMEM_BYTES>>>(
            hbuf, w2_l, b2_l, x, x, BT_, D_, DFF_, 0);
    }

    layernorm_kernel<<<BT_, 256>>>(x, lnf_g, lnf_b, xn);
    sgemm_tc_kernel<<<dim3(V_ / BN, BT_ / BM), 256, SGEMM_SMEM_BYTES>>>(
        xn, whead_t, nullptr, nullptr, out, BT_, V_, D_, 0);
}